// round 2
// baseline (speedup 1.0000x reference)
#include <cuda_runtime.h>

// ApsUp: polyphase 2x upsample + circular pad + depthwise 3x3 binomial blur,
// collapsed to a direct gather (only one of 4 phases is nonzero per batch).
//
// Shapes (fixed): inp [16,256,64,64] f32, poly [16] i32, out [16,256,128,128] f32.
//
// One block per (batch, channel): stage the 64x64 input tile in smem,
// compute 128x128 output with separable [1,2,1]/4 taps, streaming float4 stores.

#define B_ 16
#define C_ 256
#define N_ 64
#define TWO_N 128

__global__ __launch_bounds__(256) void aps_up_kernel(
    const float* __restrict__ inp,
    const int*   __restrict__ poly,
    float*       __restrict__ out)
{
    __shared__ float s[N_ * N_];   // 16 KB input channel tile

    const int bc = blockIdx.x;           // bb*256 + ch
    const int bb = bc >> 8;
    const int t  = threadIdx.x;

    const int p = __ldg(&poly[bb]);
    const int r = p & 1;                 // row phase offset (block-uniform)
    const int c = p >> 1;                // col phase offset (block-uniform)

    // Coalesced float4 load of the whole channel into smem: 1024 float4s.
    const float4* g  = reinterpret_cast<const float4*>(inp + (size_t)bc * (N_ * N_));
    float4*       s4 = reinterpret_cast<float4*>(s);
#pragma unroll
    for (int k = 0; k < 4; ++k)
        s4[k * 256 + t] = g[k * 256 + t];
    __syncthreads();

    float* obase = out + (size_t)bc * (TWO_N * TWO_N);

    // 2048 work units: (row-pair A in [0,64)) x (col-tile T in [0,32)).
    // Each unit produces a 2x4 output patch. 8 units per thread.
#pragma unroll
    for (int k = 0; k < 8; ++k) {
        const int u = k * 256 + t;
        const int T = u & 31;            // = lane id -> coalesced stores
        const int A = u >> 5;            // warp-uniform row pair

        // Input rows: A (center for row 2A+r), and A-1 (r==1) or A+1 (r==0).
        const int a1 = (A + (r ? (N_ - 1) : 1)) & (N_ - 1);

        // Input cols: 3 consecutive starting at 2T - c (circular).
        const int cs = 2 * T - c;
        const int j0 = (cs + N_)     & (N_ - 1);
        const int j1 = (cs + N_ + 1) & (N_ - 1);
        const int j2 = (cs + N_ + 2) & (N_ - 1);

        const float* r0 = s + A  * N_;
        const float* r1 = s + a1 * N_;
        const float xa0 = r0[j0], xa1 = r0[j1], xa2 = r0[j2];
        const float xb0 = r1[j0], xb1 = r1[j1], xb2 = r1[j2];

        float* op = obase + (size_t)(2 * A) * TWO_N + 4 * T;

#pragma unroll
        for (int si = 0; si < 2; ++si) {
            // Row combine for output row 2A+si.
            const float R0 = (si == r) ? 0.5f : 0.25f;   // weight on row A
            const float R1 = (si == r) ? 0.0f : 0.25f;   // weight on row a1
            const float y0 = R0 * xa0 + R1 * xb0;
            const float y1 = R0 * xa1 + R1 * xb1;
            const float y2 = R0 * xa2 + R1 * xb2;

            float4 o;
            if (c == 0) {
                // loaded cols: y0=2T, y1=2T+1, y2=2T+2
                o.x = 0.5f  * y0;
                o.y = 0.25f * (y0 + y1);
                o.z = 0.5f  * y1;
                o.w = 0.25f * (y1 + y2);
            } else {
                // loaded cols: y0=2T-1, y1=2T, y2=2T+1
                o.x = 0.25f * (y0 + y1);
                o.y = 0.5f  * y1;
                o.z = 0.25f * (y1 + y2);
                o.w = 0.5f  * y2;
            }
            __stcs(reinterpret_cast<float4*>(op + si * TWO_N), o);
        }
    }
}

extern "C" void kernel_launch(void* const* d_in, const int* in_sizes, int n_in,
                              void* d_out, int out_size)
{
    const float* inp  = (const float*)d_in[0];
    const int*   poly = (const int*)d_in[1];
    float*       out  = (float*)d_out;

    aps_up_kernel<<<B_ * C_, 256>>>(inp, poly, out);
}

// round 3
// speedup vs baseline: 1.0219x; 1.0219x over previous
#include <cuda_runtime.h>

// ApsUp: polyphase 2x upsample + circular pad + depthwise 3x3 binomial blur,
// collapsed to a direct gather (only one of 4 phases is nonzero per batch).
//
// Shapes (fixed): inp [16,256,64,64] f32, poly [16] i32, out [16,256,128,128] f32.
//
// One warp per (channel, input-row-pair A): lane L owns output cols 4L..4L+3
// of output rows 2A and 2A+1. Lane loads float2 (cols 2L,2L+1) from input rows
// A and a1 (= A+1 or A-1 circular), vertical-combines in registers, and gets the
// single horizontal neighbor via one warp shuffle per output row (circular wrap
// is exactly (lane +/- 1) & 31 since 32 lanes x 2 cols = 64 = N).

#define B_ 16
#define C_ 256
#define N_ 64
#define TWO_N 128

__global__ __launch_bounds__(256) void aps_up_kernel(
    const float* __restrict__ inp,
    const int*   __restrict__ poly,
    float*       __restrict__ out)
{
    // blockIdx.x = bc*8 + g ; warp w handles row pair A = g*8 + w
    const int bc = blockIdx.x >> 3;
    const int g  = blockIdx.x & 7;
    const int w  = threadIdx.x >> 5;
    const int L  = threadIdx.x & 31;
    const int A  = g * 8 + w;
    const int bb = bc >> 8;

    const int p = __ldg(&poly[bb]);
    const int r = p & 1;                  // row phase offset (warp-uniform)
    const int c = p >> 1;                 // col phase offset (warp-uniform)

    const int a1 = (A + (r ? (N_ - 1) : 1)) & (N_ - 1);

    const float* base = inp + (size_t)bc * (N_ * N_);
    const float2 f0 = *reinterpret_cast<const float2*>(base + A  * N_ + 2 * L);
    const float2 f1 = *reinterpret_cast<const float2*>(base + a1 * N_ + 2 * L);

    // Vertical combine (weights folded in):
    //   ve -> output row 2A + r      (weight 0.5 on row A)
    //   vo -> output row 2A + 1 - r  (weight 0.25 on rows A and a1)
    float2 ve, vo;
    ve.x = 0.5f * f0.x;
    ve.y = 0.5f * f0.y;
    vo.x = 0.25f * (f0.x + f1.x);
    vo.y = 0.25f * (f0.y + f1.y);

    float* obase = out + (size_t)bc * (TWO_N * TWO_N) + 4 * L;
    float* rowE  = obase + (size_t)(2 * A + r)     * TWO_N;
    float* rowO  = obase + (size_t)(2 * A + 1 - r) * TWO_N;

    const unsigned m = 0xFFFFFFFFu;
    if (c == 0) {
        // need v[2L+2] = lane (L+1)'s v.x  (wraps to col 0 for L=31: circular)
        const float ve2 = __shfl_sync(m, ve.x, (L + 1) & 31);
        const float vo2 = __shfl_sync(m, vo.x, (L + 1) & 31);
        float4 oe, oo;
        oe.x = 0.5f  *  ve.x;
        oe.y = 0.25f * (ve.x + ve.y);
        oe.z = 0.5f  *  ve.y;
        oe.w = 0.25f * (ve.y + ve2);
        oo.x = 0.5f  *  vo.x;
        oo.y = 0.25f * (vo.x + vo.y);
        oo.z = 0.5f  *  vo.y;
        oo.w = 0.25f * (vo.y + vo2);
        *reinterpret_cast<float4*>(rowE) = oe;
        *reinterpret_cast<float4*>(rowO) = oo;
    } else {
        // need v[2L-1] = lane (L-1)'s v.y  (wraps to col 63 for L=0: circular)
        const float vem = __shfl_sync(m, ve.y, (L + 31) & 31);
        const float vom = __shfl_sync(m, vo.y, (L + 31) & 31);
        float4 oe, oo;
        oe.x = 0.25f * (vem + ve.x);
        oe.y = 0.5f  *  ve.x;
        oe.z = 0.25f * (ve.x + ve.y);
        oe.w = 0.5f  *  ve.y;
        oo.x = 0.25f * (vom + vo.x);
        oo.y = 0.5f  *  vo.x;
        oo.z = 0.25f * (vo.x + vo.y);
        oo.w = 0.5f  *  vo.y;
        *reinterpret_cast<float4*>(rowE) = oe;
        *reinterpret_cast<float4*>(rowO) = oo;
    }
}

extern "C" void kernel_launch(void* const* d_in, const int* in_sizes, int n_in,
                              void* d_out, int out_size)
{
    const float* inp  = (const float*)d_in[0];
    const int*   poly = (const int*)d_in[1];
    float*       out  = (float*)d_out;

    // 4096 channels * 8 blocks each (8 warps/block, 1 warp per row pair)
    aps_up_kernel<<<B_ * C_ * 8, 256>>>(inp, poly, out);
}